// round 2
// baseline (speedup 1.0000x reference)
#include <cuda_runtime.h>

// CompetitiveLayer fixed-point solve + outer-product epilogue.
//
// Inputs (metadata order): AT [1024,256] f32, BT [1024,256] f32, K [256,256] f32.
// Output: C [1024,256,256] f32 where, after 51 updates of
//   AF_i = AT_i / (1 + sum_j K_ij BF_j);  BF_j = BT_j / (1 + sum_i K_ij AF_i)
// (BF initialized to BT; 50 "solve" iterations + 1 differentiable iteration),
//   C[b,i,j] = K[i,j] * AF[b,i] * BF[b,j].
//
// Parallelization: rows (batch) are fully independent -> each CTA owns 8 rows
// end-to-end through all iterations (no inter-CTA sync ever). 128 CTAs x 256 thr.
// Thread t owns index t (i for matvec1, j for matvec2) across all 8 rows
// (8 independent accumulators = good FFMA ILP). K stays in global (L2-resident,
// 256KB); both matvecs read it with contiguous/coalesced patterns:
//   matvec1: thread t sweeps row K[t][j..]   (float4 loads)
//   matvec2: for each i, lanes read K[i][t]  (fully coalesced, L1-broadcast-ish)
// AF/BF live in shared transposed as [idx][row] so the 8 per-row values are one
// 32B chunk -> two LDS.128 broadcasts per reduction step.

#define NBATCH   1024
#define NDIM     256      // nA == nB
#define N_ITERS  51       // 50 no-grad solve iterations + 1 differentiable
#define ROWS     8
#define NBLOCKS  (NBATCH / ROWS)   // 128
#define NTHREADS 256

__global__ __launch_bounds__(NTHREADS, 1)
void competitive_kernel(const float* __restrict__ AT,
                        const float* __restrict__ BT,
                        const float* __restrict__ K,
                        float* __restrict__ C)
{
    __shared__ __align__(16) float AFs[NDIM][ROWS];   // AF[idx][row]
    __shared__ __align__(16) float BFs[NDIM][ROWS];   // BF[idx][row]

    const int t  = threadIdx.x;
    const int r0 = blockIdx.x * ROWS;

    // Per-thread constants: AT/BT values at index t for this block's 8 rows.
    float at[ROWS], bt[ROWS];
#pragma unroll
    for (int r = 0; r < ROWS; r++) {
        at[r] = AT[(r0 + r) * NDIM + t];
        bt[r] = BT[(r0 + r) * NDIM + t];
    }
    // BF init = BT (AF's init is never read: first op overwrites it).
    *reinterpret_cast<float4*>(&BFs[t][0]) = make_float4(bt[0], bt[1], bt[2], bt[3]);
    *reinterpret_cast<float4*>(&BFs[t][4]) = make_float4(bt[4], bt[5], bt[6], bt[7]);
    __syncthreads();

    const float* __restrict__ Krow = K + t * NDIM;   // row i = t for matvec1

    for (int it = 0; it < N_ITERS; it++) {
        // ---- matvec1: SA[r] = sum_j K[t][j] * BF[r][j]  (thread owns i = t)
        float acc[ROWS];
#pragma unroll
        for (int r = 0; r < ROWS; r++) acc[r] = 0.0f;

#pragma unroll 8
        for (int j = 0; j < NDIM; j += 4) {
            const float4 k4 = *reinterpret_cast<const float4*>(Krow + j);
            float kv[4];
            kv[0] = k4.x; kv[1] = k4.y; kv[2] = k4.z; kv[3] = k4.w;
#pragma unroll
            for (int c = 0; c < 4; c++) {
                const float4 b0 = *reinterpret_cast<const float4*>(&BFs[j + c][0]);
                const float4 b1 = *reinterpret_cast<const float4*>(&BFs[j + c][4]);
                acc[0] += kv[c] * b0.x;  acc[1] += kv[c] * b0.y;
                acc[2] += kv[c] * b0.z;  acc[3] += kv[c] * b0.w;
                acc[4] += kv[c] * b1.x;  acc[5] += kv[c] * b1.y;
                acc[6] += kv[c] * b1.z;  acc[7] += kv[c] * b1.w;
            }
        }
        {
            float af[ROWS];
#pragma unroll
            for (int r = 0; r < ROWS; r++) af[r] = at[r] / (1.0f + acc[r]);
            *reinterpret_cast<float4*>(&AFs[t][0]) = make_float4(af[0], af[1], af[2], af[3]);
            *reinterpret_cast<float4*>(&AFs[t][4]) = make_float4(af[4], af[5], af[6], af[7]);
        }
        __syncthreads();

        // ---- matvec2: SB[r] = sum_i K[i][t] * AF[r][i]  (thread owns j = t)
#pragma unroll
        for (int r = 0; r < ROWS; r++) acc[r] = 0.0f;

#pragma unroll 8
        for (int i = 0; i < NDIM; i++) {
            const float kv = K[i * NDIM + t];          // coalesced across lanes
            const float4 a0 = *reinterpret_cast<const float4*>(&AFs[i][0]);
            const float4 a1 = *reinterpret_cast<const float4*>(&AFs[i][4]);
            acc[0] += kv * a0.x;  acc[1] += kv * a0.y;
            acc[2] += kv * a0.z;  acc[3] += kv * a0.w;
            acc[4] += kv * a1.x;  acc[5] += kv * a1.y;
            acc[6] += kv * a1.z;  acc[7] += kv * a1.w;
        }
        {
            float bf[ROWS];
#pragma unroll
            for (int r = 0; r < ROWS; r++) bf[r] = bt[r] / (1.0f + acc[r]);
            *reinterpret_cast<float4*>(&BFs[t][0]) = make_float4(bf[0], bf[1], bf[2], bf[3]);
            *reinterpret_cast<float4*>(&BFs[t][4]) = make_float4(bf[4], bf[5], bf[6], bf[7]);
        }
        __syncthreads();
    }

    // ---- Epilogue: C[b,i,j] = K[i,j] * AF[b,i] * BF[b,j]; thread owns j = t.
    float bf[ROWS];
    {
        const float4 b0 = *reinterpret_cast<const float4*>(&BFs[t][0]);
        const float4 b1 = *reinterpret_cast<const float4*>(&BFs[t][4]);
        bf[0] = b0.x; bf[1] = b0.y; bf[2] = b0.z; bf[3] = b0.w;
        bf[4] = b1.x; bf[5] = b1.y; bf[6] = b1.z; bf[7] = b1.w;
    }

#pragma unroll 4
    for (int i = 0; i < NDIM; i++) {
        const float kv = K[i * NDIM + t];              // coalesced, L2-hot
        const float4 a0 = *reinterpret_cast<const float4*>(&AFs[i][0]);
        const float4 a1 = *reinterpret_cast<const float4*>(&AFs[i][4]);
        float a[ROWS];
        a[0] = a0.x; a[1] = a0.y; a[2] = a0.z; a[3] = a0.w;
        a[4] = a1.x; a[5] = a1.y; a[6] = a1.z; a[7] = a1.w;
        const int base = i * NDIM + t;
#pragma unroll
        for (int r = 0; r < ROWS; r++) {
            // coalesced 128B stores per (r, i) across the warp
            C[(size_t)(r0 + r) * (NDIM * NDIM) + base] = kv * a[r] * bf[r];
        }
    }
}

extern "C" void kernel_launch(void* const* d_in, const int* in_sizes, int n_in,
                              void* d_out, int out_size)
{
    const float* AT = (const float*)d_in[0];
    const float* BT = (const float*)d_in[1];
    const float* K  = (const float*)d_in[2];
    float*       C  = (float*)d_out;

    competitive_kernel<<<NBLOCKS, NTHREADS>>>(AT, BT, K, C);
}

// round 3
// speedup vs baseline: 1.2808x; 1.2808x over previous
#include <cuda_runtime.h>

// CompetitiveLayer fixed-point solve + outer-product epilogue — round 2.
//
// R1 finding: L1 69.8% busy — matvec1's K[t*256+j] loads are anti-coalesced
// (32 lines/warp/load). Fix: pre-transpose K into __device__ scratch KT so
// BOTH matvecs read lane-contiguous. Also: packed fma.rn.f32x2 halves FFMA
// issue slots; __fdividef in the 50 contracting no-grad iterations (exact
// div.rn kept for the final differentiable iteration).
//
// Inputs: AT [1024,256] f32, BT [1024,256] f32, K [256,256] f32.
// Output: C [1024,256,256] f32.

#define NBATCH   1024
#define NDIM     256
#define N_ITERS  51        // 50 no-grad + 1 differentiable
#define ROWS     8
#define NBLOCKS  (NBATCH / ROWS)   // 128
#define NTHREADS 256

__device__ __align__(16) float KT_g[NDIM * NDIM];   // K transposed (scratch)

// ---- f32x2 packed helpers (Blackwell; PTX-only) ----
__device__ __forceinline__ unsigned long long pack2(float x) {
    unsigned long long r;
    asm("mov.b64 %0, {%1, %1};" : "=l"(r) : "f"(x));
    return r;
}
__device__ __forceinline__ unsigned long long fma2(unsigned long long a,
                                                   unsigned long long b,
                                                   unsigned long long c) {
    unsigned long long d;
    asm("fma.rn.f32x2 %0, %1, %2, %3;" : "=l"(d) : "l"(a), "l"(b), "l"(c));
    return d;
}
__device__ __forceinline__ void unpack2(unsigned long long v, float& lo, float& hi) {
    asm("mov.b64 {%0, %1}, %2;" : "=f"(lo), "=f"(hi) : "l"(v));
}

// ---- K transpose: 32x32 shared tiles, both sides coalesced ----
__global__ void transpose_kernel(const float* __restrict__ K) {
    __shared__ float tile[32][33];
    const int bx = blockIdx.x * 32, by = blockIdx.y * 32;
    const int tx = threadIdx.x, ty = threadIdx.y;   // 32 x 8
#pragma unroll
    for (int r = 0; r < 32; r += 8)
        tile[ty + r][tx] = K[(by + ty + r) * NDIM + bx + tx];
    __syncthreads();
#pragma unroll
    for (int r = 0; r < 32; r += 8)
        KT_g[(bx + ty + r) * NDIM + by + tx] = tile[tx][ty + r];
}

__global__ __launch_bounds__(NTHREADS, 1)
void competitive_kernel(const float* __restrict__ AT,
                        const float* __restrict__ BT,
                        const float* __restrict__ K,
                        float* __restrict__ C)
{
    __shared__ __align__(16) float AFs[NDIM][ROWS];   // AF[idx][row] pairs = f32x2
    __shared__ __align__(16) float BFs[NDIM][ROWS];

    const int t  = threadIdx.x;
    const int r0 = blockIdx.x * ROWS;

    float at[ROWS], bt[ROWS];
#pragma unroll
    for (int r = 0; r < ROWS; r++) {
        at[r] = AT[(r0 + r) * NDIM + t];
        bt[r] = BT[(r0 + r) * NDIM + t];
    }
    // BF init = BT (first half-step only reads BF).
    *reinterpret_cast<float4*>(&BFs[t][0]) = make_float4(bt[0], bt[1], bt[2], bt[3]);
    *reinterpret_cast<float4*>(&BFs[t][4]) = make_float4(bt[4], bt[5], bt[6], bt[7]);
    __syncthreads();

    for (int it = 0; it < N_ITERS; it++) {
        const bool last = (it == N_ITERS - 1);

        // ---- matvec1: SA[r] = sum_j K[t][j]*BF[r][j] = sum_j KT[j][t]*BF[r][j]
        unsigned long long acc[4];
#pragma unroll
        for (int q = 0; q < 4; q++) acc[q] = 0ull;

#pragma unroll 8
        for (int j = 0; j < NDIM; j++) {
            const float kv = KT_g[j * NDIM + t];                 // coalesced
            const unsigned long long kk = pack2(kv);
            const ulonglong2 b01 = *reinterpret_cast<const ulonglong2*>(&BFs[j][0]);
            const ulonglong2 b23 = *reinterpret_cast<const ulonglong2*>(&BFs[j][4]);
            acc[0] = fma2(kk, b01.x, acc[0]);
            acc[1] = fma2(kk, b01.y, acc[1]);
            acc[2] = fma2(kk, b23.x, acc[2]);
            acc[3] = fma2(kk, b23.y, acc[3]);
        }
        {
            float s[ROWS], af[ROWS];
#pragma unroll
            for (int q = 0; q < 4; q++) unpack2(acc[q], s[2*q], s[2*q+1]);
            if (last) {
#pragma unroll
                for (int r = 0; r < ROWS; r++) af[r] = at[r] / (1.0f + s[r]);
            } else {
#pragma unroll
                for (int r = 0; r < ROWS; r++) af[r] = __fdividef(at[r], 1.0f + s[r]);
            }
            *reinterpret_cast<float4*>(&AFs[t][0]) = make_float4(af[0], af[1], af[2], af[3]);
            *reinterpret_cast<float4*>(&AFs[t][4]) = make_float4(af[4], af[5], af[6], af[7]);
        }
        __syncthreads();

        // ---- matvec2: SB[r] = sum_i K[i][t]*AF[r][i]   (K direct, coalesced)
#pragma unroll
        for (int q = 0; q < 4; q++) acc[q] = 0ull;

#pragma unroll 8
        for (int i = 0; i < NDIM; i++) {
            const float kv = K[i * NDIM + t];                    // coalesced
            const unsigned long long kk = pack2(kv);
            const ulonglong2 a01 = *reinterpret_cast<const ulonglong2*>(&AFs[i][0]);
            const ulonglong2 a23 = *reinterpret_cast<const ulonglong2*>(&AFs[i][4]);
            acc[0] = fma2(kk, a01.x, acc[0]);
            acc[1] = fma2(kk, a01.y, acc[1]);
            acc[2] = fma2(kk, a23.x, acc[2]);
            acc[3] = fma2(kk, a23.y, acc[3]);
        }
        {
            float s[ROWS], bf[ROWS];
#pragma unroll
            for (int q = 0; q < 4; q++) unpack2(acc[q], s[2*q], s[2*q+1]);
            if (last) {
#pragma unroll
                for (int r = 0; r < ROWS; r++) bf[r] = bt[r] / (1.0f + s[r]);
            } else {
#pragma unroll
                for (int r = 0; r < ROWS; r++) bf[r] = __fdividef(bt[r], 1.0f + s[r]);
            }
            *reinterpret_cast<float4*>(&BFs[t][0]) = make_float4(bf[0], bf[1], bf[2], bf[3]);
            *reinterpret_cast<float4*>(&BFs[t][4]) = make_float4(bf[4], bf[5], bf[6], bf[7]);
        }
        __syncthreads();
    }

    // ---- Epilogue: C[b,i,j] = K[i,j]*AF[b,i]*BF[b,j]; thread owns j = t.
    float bf[ROWS];
    {
        const float4 b0 = *reinterpret_cast<const float4*>(&BFs[t][0]);
        const float4 b1 = *reinterpret_cast<const float4*>(&BFs[t][4]);
        bf[0] = b0.x; bf[1] = b0.y; bf[2] = b0.z; bf[3] = b0.w;
        bf[4] = b1.x; bf[5] = b1.y; bf[6] = b1.z; bf[7] = b1.w;
    }

#pragma unroll 4
    for (int i = 0; i < NDIM; i++) {
        const float kv = K[i * NDIM + t];                        // coalesced, L2-hot
        const float4 a0 = *reinterpret_cast<const float4*>(&AFs[i][0]);
        const float4 a1 = *reinterpret_cast<const float4*>(&AFs[i][4]);
        float a[ROWS];
        a[0] = a0.x; a[1] = a0.y; a[2] = a0.z; a[3] = a0.w;
        a[4] = a1.x; a[5] = a1.y; a[6] = a1.z; a[7] = a1.w;
        const int base = i * NDIM + t;
#pragma unroll
        for (int r = 0; r < ROWS; r++)
            C[(size_t)(r0 + r) * (NDIM * NDIM) + base] = kv * a[r] * bf[r];
    }
}

extern "C" void kernel_launch(void* const* d_in, const int* in_sizes, int n_in,
                              void* d_out, int out_size)
{
    const float* AT = (const float*)d_in[0];
    const float* BT = (const float*)d_in[1];
    const float* K  = (const float*)d_in[2];
    float*       C  = (float*)d_out;

    transpose_kernel<<<dim3(NDIM / 32, NDIM / 32), dim3(32, 8)>>>(K);
    competitive_kernel<<<NBLOCKS, NTHREADS>>>(AT, BT, K, C);
}